// round 15
// baseline (speedup 1.0000x reference)
#include <cuda_runtime.h>
#include <cuda_fp16.h>
#include <cstdint>
#include <math.h>

#define NUM_EXPERTS 8
#define D_MODEL 1024
#define D_FF 4096
#define GROUPS 4
#define TOKENS 16384
#define CHUNK 2048

// ---------------- scratch (device globals) ----------------
// fp16 fragment-tiled layouts (u32 = half2):
//  A-frag: [mtile(16 rows)][K/16][128 u32]  (16x16 block, lane*4 -> lds.128)
//  B-frag: [ntile(8 cols)][K/16][64 u32]    (16x8 block,  lane*2 -> lds.64)
__device__ uint32_t g_xr [(size_t)(GROUPS * TOKENS / 16) * (D_MODEL / 16) * 128]; // 134 MB
__device__ uint32_t g_w1t[(size_t)NUM_EXPERTS * (D_FF / 8) * (D_MODEL / 16) * 64]; // 67 MB
__device__ uint32_t g_w2t[(size_t)NUM_EXPERTS * (D_MODEL / 8) * (D_FF / 16) * 64]; // 67 MB
__device__ uint32_t g_h  [(size_t)(GROUPS * TOKENS / 16) * (D_FF / 16) * 128];     // 536 MB

// ---------------- helpers ----------------
__device__ __forceinline__ uint32_t smem_u32(const void* p) {
    uint32_t a;
    asm("{ .reg .u64 t; cvta.to.shared.u64 t, %1; cvt.u32.u64 %0, t; }" : "=r"(a) : "l"(p));
    return a;
}

__device__ __forceinline__ uint32_t pack_h2(float lo, float hi) {
    uint32_t u;
    asm("cvt.rn.f16x2.f32 %0, %1, %2;" : "=r"(u) : "f"(hi), "f"(lo));  // d = {hi, lo}
    return u;
}

__device__ __forceinline__ void mma_fp16(float* c, const uint32_t* a, const uint32_t* b) {
    asm volatile(
        "mma.sync.aligned.m16n8k16.row.col.f32.f16.f16.f32 "
        "{%0,%1,%2,%3}, {%4,%5,%6,%7}, {%8,%9}, {%0,%1,%2,%3};"
        : "+f"(c[0]), "+f"(c[1]), "+f"(c[2]), "+f"(c[3])
        : "r"(a[0]), "r"(a[1]), "r"(a[2]), "r"(a[3]), "r"(b[0]), "r"(b[1]));
}

// ---------------- prep kernels (unchanged) ----------------
__global__ void __launch_bounds__(256) prep_A(const float* __restrict__ src,
                                              uint32_t* __restrict__ dst, int K) {
    __shared__ float t[16][132];
    const int mt = blockIdx.y, kb8 = blockIdx.x;
    const int tid = threadIdx.x;
    const int K16 = K >> 4;
#pragma unroll
    for (int i = 0; i < 8; i++) {
        int lin = i * 256 + tid;
        int r = lin >> 7, c = lin & 127;
        t[r][c] = src[(size_t)(mt * 16 + r) * K + kb8 * 128 + c];
    }
    __syncthreads();
#pragma unroll
    for (int i = 0; i < 4; i++) {
        int lin = i * 256 + tid;                 // 1024 u32 outputs
        int kbl = lin >> 7, pos = lin & 127;
        int lane = pos >> 2, reg = pos & 3;
        int gl = lane >> 2, tt = lane & 3;
        int r = gl + (reg & 1) * 8;
        int kl = kbl * 16 + 2 * tt + (reg >> 1) * 8;
        dst[((size_t)mt * K16 + kb8 * 8 + kbl) * 128 + pos] = pack_h2(t[r][kl], t[r][kl + 1]);
    }
}

__global__ void __launch_bounds__(256) prep_B(const float* __restrict__ src,
                                              uint32_t* __restrict__ dst, int K, int N) {
    __shared__ float t[16][260];
    const int kb = blockIdx.y, nb = blockIdx.x, e = blockIdx.z;
    const int tid = threadIdx.x;
    const int K16 = K >> 4;
    const float* sp = src + (size_t)e * K * N;
    uint32_t* dp = dst + (size_t)e * (N >> 3) * K16 * 64;
#pragma unroll
    for (int i = 0; i < 16; i++) {
        int lin = i * 256 + tid;
        int r = lin >> 8, c = lin & 255;
        t[r][c] = sp[(size_t)(kb * 16 + r) * N + nb * 256 + c];
    }
    __syncthreads();
#pragma unroll
    for (int i = 0; i < 8; i++) {
        int lin = i * 256 + tid;                 // 2048 u32 outputs
        int ntl = lin >> 6, pos = lin & 63;
        int lane = pos >> 1, reg = pos & 1;
        int gl = lane >> 2, tt = lane & 3;
        int n = ntl * 8 + gl;
        int kl = 2 * tt + reg * 8;
        dp[((size_t)(nb * 32 + ntl) * K16 + kb) * 64 + pos] = pack_h2(t[kl][n], t[kl + 1][n]);
    }
}

// ---------------- GEMM ----------------
// CTA tile 128x64, Kc=64 (4 kt of K=16), 2-stage cp.async, kc unrolled x2, 3 CTAs/SM.
// 8 warps (2M x 4N), warp tile 64x16 (32 acc regs).
static constexpr int S_A_BYTES = 16384;             // 8 mt * 4 kt * 512B
static constexpr int S_B_BYTES = 8192;              // 8 nt * 4 kt * 256B
static constexpr int S_STAGE   = S_A_BYTES + S_B_BYTES;   // 24576
static constexpr int DSMEM     = 2 * S_STAGE + 512;       // 49664 (x3 CTA = 149KB < 228KB)

template <bool GELU>
__global__ void __launch_bounds__(256, 3)
gemm_fp16(const uint32_t* __restrict__ A, const uint32_t* __restrict__ B,
          const float* __restrict__ bias, void* __restrict__ Cv,
          int K, int N) {
    extern __shared__ char smem[];
    const uint32_t sb = smem_u32(smem);
    const int tid = threadIdx.x;
    const int wid = tid >> 5;
    const int lid = tid & 31;
    const int gl = lid >> 2, tt = lid & 3;
    const int wm = wid & 1;                          // 0/1: M half (64 rows)
    const int wn = wid >> 1;                         // 0..3: N quarter (16 cols = 2 nt)

    const int ge = blockIdx.z;
    const int gg = ge >> 3, e = ge & 7;
    const int K16 = K >> 4;
    const long row_base = (long)gg * TOKENS + (long)e * CHUNK + (long)blockIdx.y * 128;
    const uint32_t* Abase = A + (size_t)(row_base >> 4) * K16 * 128;
    const uint32_t* Bbase = B + (size_t)(e * (N >> 3) + blockIdx.x * 8) * K16 * 64;

    // hoisted per-thread copy addressing
    const int w5 = tid >> 5, cc = tid & 31;          // A: 8 groups x 32 thr, 4 chunks each
    const int b5 = tid >> 4, bc = tid & 15;          // B: 16 groups x 16 thr, 2 chunks each
    const size_t aStride = (size_t)K16 * 128;        // u32 per A frag-tile row
    const size_t bStride = (size_t)K16 * 64;         // u32 per B frag-tile row
    const uint32_t* pA = Abase + (size_t)(w5 >> 2) * aStride + (w5 & 3) * 128 + cc * 4;
    const uint32_t* pB = Bbase + (size_t)(b5 >> 2) * bStride + (b5 & 3) * 64 + bc * 4;
    const uint32_t aDst = sb + (uint32_t)(w5 * 512 + cc * 16);
    const uint32_t bDst = sb + (uint32_t)(S_A_BYTES + b5 * 256 + bc * 16);

    float* sbias = (float*)(smem + 2 * S_STAGE);
    if (tid < 64) sbias[tid] = bias[e * N + blockIdx.x * 64 + tid];

    // warp-level lds base offsets (bytes, relative to stage base)
    const uint32_t aw_off = (uint32_t)(wm * 8192 + lid * 16);
    const uint32_t bw_off = (uint32_t)(S_A_BYTES + wn * 2048 + lid * 8);

    const int NK = K >> 6;

#define LOAD_STAGE(ST, KC) do {                                                   \
    const uint32_t _kA = (uint32_t)(KC) * 512;                                    \
    const uint32_t _kB = (uint32_t)(KC) * 256;                                    \
    _Pragma("unroll")                                                             \
    for (int i = 0; i < 4; i++)                                                   \
        asm volatile("cp.async.cg.shared.global [%0], [%1], 16;"                  \
                     :: "r"(aDst + (ST) + i * 4096),                              \
                        "l"(pA + _kA + i * 2 * aStride));                         \
    _Pragma("unroll")                                                             \
    for (int i = 0; i < 2; i++)                                                   \
        asm volatile("cp.async.cg.shared.global [%0], [%1], 16;"                  \
                     :: "r"(bDst + (ST) + i * 4096),                              \
                        "l"(pB + _kB + i * 4 * bStride));                         \
    asm volatile("cp.async.commit_group;" ::: "memory");                          \
} while (0)

#define COMPUTE(ST) do {                                                          \
    const uint32_t sA = sb + (ST) + aw_off;                                       \
    const uint32_t sB = sb + (ST) + bw_off;                                       \
    _Pragma("unroll")                                                             \
    for (int kt = 0; kt < 4; kt++) {                                              \
        uint32_t af[4][4], bf[2][2];                                              \
        _Pragma("unroll")                                                         \
        for (int mt = 0; mt < 4; mt++)                                            \
            asm volatile("ld.shared.v4.b32 {%0,%1,%2,%3}, [%4];"                  \
                         : "=r"(af[mt][0]), "=r"(af[mt][1]),                      \
                           "=r"(af[mt][2]), "=r"(af[mt][3])                       \
                         : "r"(sA + (uint32_t)((mt * 4 + kt) * 512)));            \
        _Pragma("unroll")                                                         \
        for (int nt = 0; nt < 2; nt++)                                            \
            asm volatile("ld.shared.v2.b32 {%0,%1}, [%2];"                        \
                         : "=r"(bf[nt][0]), "=r"(bf[nt][1])                       \
                         : "r"(sB + (uint32_t)((nt * 4 + kt) * 256)));            \
        _Pragma("unroll")                                                         \
        for (int mt = 0; mt < 4; mt++)                                            \
            _Pragma("unroll")                                                     \
            for (int nt = 0; nt < 2; nt++)                                        \
                mma_fp16(acc[mt][nt], af[mt], bf[nt]);                            \
    }                                                                             \
} while (0)

    LOAD_STAGE(0u, 0);

    float acc[4][2][4];
#pragma unroll
    for (int i = 0; i < 4; i++)
#pragma unroll
        for (int j = 0; j < 2; j++)
#pragma unroll
            for (int q = 0; q < 4; q++) acc[i][j][q] = 0.0f;

    for (int kc = 0; kc < NK; kc += 2) {
        asm volatile("cp.async.wait_group 0;" ::: "memory");
        __syncthreads();
        if (kc + 1 < NK) LOAD_STAGE((uint32_t)S_STAGE, kc + 1);
        COMPUTE(0u);

        asm volatile("cp.async.wait_group 0;" ::: "memory");
        __syncthreads();
        if (kc + 2 < NK) LOAD_STAGE(0u, kc + 2);
        COMPUTE((uint32_t)S_STAGE);
    }
#undef LOAD_STAGE
#undef COMPUTE

    // ---- epilogue ----
#pragma unroll
    for (int mt = 0; mt < 4; mt++) {
        if (GELU) {
            uint32_t* C = (uint32_t*)Cv;
            // The warp's two nt blocks (16 H-cols) form one fp16 A-frag block of H.
            float v[2][4];
#pragma unroll
            for (int h = 0; h < 2; h++) {
                const int col0 = wn * 16 + h * 8 + 2 * tt;
#pragma unroll
                for (int q = 0; q < 4; q++) {
                    float x = acc[mt][h][q] + sbias[col0 + (q & 1)];
                    x = 0.5f * x * (1.0f + erff(x * 0.70710678118654752f));
                    v[h][q] = x;
                }
            }
            uint32_t p0 = pack_h2(v[0][0], v[0][1]);   // row gl,   k 2tt,2tt+1
            uint32_t p1 = pack_h2(v[0][2], v[0][3]);   // row gl+8, k 2tt,2tt+1
            uint32_t p2 = pack_h2(v[1][0], v[1][1]);   // row gl,   k 2tt+8,2tt+9
            uint32_t p3 = pack_h2(v[1][2], v[1][3]);   // row gl+8, k 2tt+8,2tt+9
            const size_t Mtile = (size_t)(row_base >> 4) + wm * 4 + mt;
            const int kb2 = blockIdx.x * 4 + wn;
            uint4* dst = reinterpret_cast<uint4*>(
                C + (Mtile * (size_t)(N >> 4) + kb2) * 128 + lid * 4);
            *dst = make_uint4(p0, p1, p2, p3);
        } else {
            float* C = (float*)Cv;
#pragma unroll
            for (int nt = 0; nt < 2; nt++) {
                const int col0 = wn * 16 + nt * 8 + 2 * tt;
                float v[4];
#pragma unroll
                for (int q = 0; q < 4; q++)
                    v[q] = acc[mt][nt][q] + sbias[col0 + (q & 1)];
                const int r0 = wm * 64 + mt * 16 + gl;
                long R0 = row_base + r0;
                int c = blockIdx.x * 64 + col0;
                *reinterpret_cast<float2*>(&C[(size_t)R0 * N + c]) = make_float2(v[0], v[1]);
                *reinterpret_cast<float2*>(&C[(size_t)(R0 + 8) * N + c]) = make_float2(v[2], v[3]);
            }
        }
    }
}

// ---------------- launch ----------------
extern "C" void kernel_launch(void* const* d_in, const int* in_sizes, int n_in,
                              void* d_out, int out_size) {
    const float* x  = (const float*)d_in[0];
    const float* w1 = (const float*)d_in[1];
    const float* b1 = (const float*)d_in[2];
    const float* w2 = (const float*)d_in[3];
    const float* b2 = (const float*)d_in[4];
    float* out = (float*)d_out;

    uint32_t *p_xr, *p_w1t, *p_w2t, *p_h;
    cudaGetSymbolAddress((void**)&p_xr,  g_xr);
    cudaGetSymbolAddress((void**)&p_w1t, g_w1t);
    cudaGetSymbolAddress((void**)&p_w2t, g_w2t);
    cudaGetSymbolAddress((void**)&p_h,   g_h);

    cudaFuncSetAttribute(gemm_fp16<true>,  cudaFuncAttributeMaxDynamicSharedMemorySize, DSMEM);
    cudaFuncSetAttribute(gemm_fp16<false>, cudaFuncAttributeMaxDynamicSharedMemorySize, DSMEM);

    // pack x into fp16 A-frag layout (65536 rows, K=1024)
    prep_A<<<dim3(D_MODEL / 128, GROUPS * TOKENS / 16), 256>>>(x, p_xr, D_MODEL);
    // pack w1 [e][1024][4096] (k=d_model, n=d_ff) into fp16 B-frag
    prep_B<<<dim3(D_FF / 256, D_MODEL / 16, NUM_EXPERTS), 256>>>(w1, p_w1t, D_MODEL, D_FF);
    // pack w2 [e][4096][1024] (k=d_ff, n=d_model) into fp16 B-frag
    prep_B<<<dim3(D_MODEL / 256, D_FF / 16, NUM_EXPERTS), 256>>>(w2, p_w2t, D_FF, D_MODEL);

    // GEMM1: per (g,e): [2048 x 1024] @ [1024 x 4096] + b1, gelu -> H (fp16 A-frag)
    gemm_fp16<true><<<dim3(D_FF / 64, CHUNK / 128, GROUPS * NUM_EXPERTS), 256, DSMEM>>>(
        p_xr, p_w1t, b1, p_h, D_MODEL, D_FF);
    // GEMM2: per (g,e): [2048 x 4096] @ [4096 x 1024] + b2 -> out (row-major f32)
    gemm_fp16<false><<<dim3(D_MODEL / 64, CHUNK / 128, GROUPS * NUM_EXPERTS), 256, DSMEM>>>(
        p_h, p_w2t, b2, out, D_FF, D_MODEL);
}

// round 16
// speedup vs baseline: 1.2222x; 1.2222x over previous
#include <cuda_runtime.h>
#include <cuda_fp16.h>
#include <cstdint>
#include <math.h>

#define NUM_EXPERTS 8
#define D_MODEL 1024
#define D_FF 4096
#define GROUPS 4
#define TOKENS 16384
#define CHUNK 2048

// ---------------- scratch (device globals) ----------------
// fp16 fragment-tiled layouts (u32 = half2):
//  A-frag: [mtile(16 rows)][K/16][128 u32]   (16x16 block, lane*4 -> lds.128)
//  B-pair: [ntp(16 cols)][K/16][128 u32]     (two 16x8 frags interleaved, lane*4 -> lds.128)
__device__ uint32_t g_xr [(size_t)(GROUPS * TOKENS / 16) * (D_MODEL / 16) * 128]; // 134 MB
__device__ uint32_t g_w1t[(size_t)(NUM_EXPERTS * D_FF / 16) * (D_MODEL / 16) * 128]; // 67 MB
__device__ uint32_t g_w2t[(size_t)(NUM_EXPERTS * D_MODEL / 16) * (D_FF / 16) * 128]; // 67 MB
__device__ uint32_t g_h  [(size_t)(GROUPS * TOKENS / 16) * (D_FF / 16) * 128];     // 536 MB

// ---------------- helpers ----------------
__device__ __forceinline__ uint32_t smem_u32(const void* p) {
    uint32_t a;
    asm("{ .reg .u64 t; cvta.to.shared.u64 t, %1; cvt.u32.u64 %0, t; }" : "=r"(a) : "l"(p));
    return a;
}

__device__ __forceinline__ uint32_t pack_h2(float lo, float hi) {
    uint32_t u;
    asm("cvt.rn.f16x2.f32 %0, %1, %2;" : "=r"(u) : "f"(hi), "f"(lo));  // d = {hi, lo}
    return u;
}

__device__ __forceinline__ void mma_fp16(float* c, const uint32_t* a, const uint32_t* b) {
    asm volatile(
        "mma.sync.aligned.m16n8k16.row.col.f32.f16.f16.f32 "
        "{%0,%1,%2,%3}, {%4,%5,%6,%7}, {%8,%9}, {%0,%1,%2,%3};"
        : "+f"(c[0]), "+f"(c[1]), "+f"(c[2]), "+f"(c[3])
        : "r"(a[0]), "r"(a[1]), "r"(a[2]), "r"(a[3]), "r"(b[0]), "r"(b[1]));
}

// ---------------- prep kernels ----------------
// A-frag pack: src row-major [M][K] f32 -> dst u32 [mt][K/16][128], fp16 RN.
__global__ void __launch_bounds__(256) prep_A(const float* __restrict__ src,
                                              uint32_t* __restrict__ dst, int K) {
    __shared__ float t[16][132];
    const int mt = blockIdx.y, kb8 = blockIdx.x;
    const int tid = threadIdx.x;
    const int K16 = K >> 4;
#pragma unroll
    for (int i = 0; i < 8; i++) {
        int lin = i * 256 + tid;
        int r = lin >> 7, c = lin & 127;
        t[r][c] = src[(size_t)(mt * 16 + r) * K + kb8 * 128 + c];
    }
    __syncthreads();
#pragma unroll
    for (int i = 0; i < 4; i++) {
        int lin = i * 256 + tid;                 // 1024 u32 outputs
        int kbl = lin >> 7, pos = lin & 127;
        int lane = pos >> 2, reg = pos & 3;
        int gl = lane >> 2, tt = lane & 3;
        int r = gl + (reg & 1) * 8;
        int kl = kbl * 16 + 2 * tt + (reg >> 1) * 8;
        dst[((size_t)mt * K16 + kb8 * 8 + kbl) * 128 + pos] = pack_h2(t[r][kl], t[r][kl + 1]);
    }
}

// B-pair pack: src row-major [K][N] f32 (per expert) -> dst u32 [ntp][K/16][128], fp16 RN.
// ntp = pair of adjacent 8-col n-blocks; pos = lane*4 + h*2 + reg (h selects frag in pair).
__global__ void __launch_bounds__(256) prep_B(const float* __restrict__ src,
                                              uint32_t* __restrict__ dst, int K, int N) {
    __shared__ float t[16][260];
    const int kb = blockIdx.y, nb = blockIdx.x, e = blockIdx.z;
    const int tid = threadIdx.x;
    const int K16 = K >> 4;
    const float* sp = src + (size_t)e * K * N;
    uint32_t* dp = dst + (size_t)e * (N >> 4) * K16 * 128;
#pragma unroll
    for (int i = 0; i < 16; i++) {
        int lin = i * 256 + tid;
        int r = lin >> 8, c = lin & 255;
        t[r][c] = sp[(size_t)(kb * 16 + r) * N + nb * 256 + c];
    }
    __syncthreads();
#pragma unroll
    for (int i = 0; i < 8; i++) {
        int lin = i * 256 + tid;                 // 2048 u32 outputs (16 ntp x 128)
        int ntp = lin >> 7, pos = lin & 127;
        int lane = pos >> 2, sub = pos & 3;
        int h = sub >> 1, reg = sub & 1;
        int gl = lane >> 2, tt = lane & 3;
        int n = (2 * ntp + h) * 8 + gl;
        int kl = 2 * tt + reg * 8;
        dp[((size_t)(nb * 16 + ntp) * K16 + kb) * 128 + pos] = pack_h2(t[kl][n], t[kl + 1][n]);
    }
}

// ---------------- GEMM ----------------
// CTA tile 128x128, Kc=64 (4 kt of K=16), 2-stage cp.async, kc unrolled x2, 2 CTAs/SM.
// 8 warps (2M x 4N), warp tile 64x32. B in pair layout: 2 lds.128 per kt instead of 4 lds.64.
static constexpr int S_A_BYTES = 16384;             // 8 mt * 4 kt * 512B
static constexpr int S_B_BYTES = 16384;             // 8 ntp * 4 kt * 512B
static constexpr int S_STAGE   = S_A_BYTES + S_B_BYTES;   // 32768
static constexpr int DSMEM     = 2 * S_STAGE + 1024;      // 66560

template <bool GELU>
__global__ void __launch_bounds__(256, 2)
gemm_fp16(const uint32_t* __restrict__ A, const uint32_t* __restrict__ B,
          const float* __restrict__ bias, void* __restrict__ Cv,
          int K, int N) {
    extern __shared__ char smem[];
    const uint32_t sb = smem_u32(smem);
    const int tid = threadIdx.x;
    const int wid = tid >> 5;
    const int lid = tid & 31;
    const int gl = lid >> 2, tt = lid & 3;
    const int wm = wid & 1;                          // 0/1: M half (64 rows)
    const int wn = wid >> 1;                         // 0..3: N quarter (32 cols = 2 ntp)

    const int ge = blockIdx.z;
    const int gg = ge >> 3, e = ge & 7;
    const int K16 = K >> 4;
    const long row_base = (long)gg * TOKENS + (long)e * CHUNK + (long)blockIdx.y * 128;
    const uint32_t* Abase = A + (size_t)(row_base >> 4) * K16 * 128;
    const uint32_t* Bbase = B + (size_t)(e * (N >> 4) + blockIdx.x * 8) * K16 * 128;

    // hoisted per-thread copy addressing (A and B share the same 8-group x 32-thread shape)
    const int w5 = tid >> 5, cc = tid & 31;
    const size_t aStride = (size_t)K16 * 128;        // u32 per A frag-tile row
    const size_t bStride = (size_t)K16 * 128;        // u32 per B pair-tile row
    const uint32_t* pA = Abase + (size_t)(w5 >> 2) * aStride + (w5 & 3) * 128 + cc * 4;
    const uint32_t* pB = Bbase + (size_t)(w5 >> 2) * bStride + (w5 & 3) * 128 + cc * 4;
    const uint32_t aDst = sb + (uint32_t)(w5 * 512 + cc * 16);
    const uint32_t bDst = sb + (uint32_t)(S_A_BYTES + w5 * 512 + cc * 16);

    float* sbias = (float*)(smem + 2 * S_STAGE);
    if (tid < 128) sbias[tid] = bias[e * N + blockIdx.x * 128 + tid];

    // warp-level lds base offsets (bytes, relative to stage base)
    const uint32_t aw_off = (uint32_t)(wm * 8192 + lid * 16);
    const uint32_t bw_off = (uint32_t)(S_A_BYTES + wn * 4096 + lid * 16);

    const int NK = K >> 6;

#define LOAD_STAGE(ST, KC) do {                                                   \
    const uint32_t _k = (uint32_t)(KC) * 512;                                     \
    _Pragma("unroll")                                                             \
    for (int i = 0; i < 4; i++)                                                   \
        asm volatile("cp.async.cg.shared.global [%0], [%1], 16;"                  \
                     :: "r"(aDst + (ST) + i * 4096),                              \
                        "l"(pA + _k + i * 2 * aStride));                          \
    _Pragma("unroll")                                                             \
    for (int i = 0; i < 4; i++)                                                   \
        asm volatile("cp.async.cg.shared.global [%0], [%1], 16;"                  \
                     :: "r"(bDst + (ST) + i * 4096),                              \
                        "l"(pB + _k + i * 2 * bStride));                          \
    asm volatile("cp.async.commit_group;" ::: "memory");                          \
} while (0)

#define COMPUTE(ST) do {                                                          \
    const uint32_t sA = sb + (ST) + aw_off;                                       \
    const uint32_t sB = sb + (ST) + bw_off;                                       \
    _Pragma("unroll")                                                             \
    for (int kt = 0; kt < 4; kt++) {                                              \
        uint32_t af[4][4], bfp[2][4];                                             \
        _Pragma("unroll")                                                         \
        for (int mt = 0; mt < 4; mt++)                                            \
            asm volatile("ld.shared.v4.b32 {%0,%1,%2,%3}, [%4];"                  \
                         : "=r"(af[mt][0]), "=r"(af[mt][1]),                      \
                           "=r"(af[mt][2]), "=r"(af[mt][3])                       \
                         : "r"(sA + (uint32_t)((mt * 4 + kt) * 512)));            \
        _Pragma("unroll")                                                         \
        for (int p = 0; p < 2; p++)                                               \
            asm volatile("ld.shared.v4.b32 {%0,%1,%2,%3}, [%4];"                  \
                         : "=r"(bfp[p][0]), "=r"(bfp[p][1]),                      \
                           "=r"(bfp[p][2]), "=r"(bfp[p][3])                       \
                         : "r"(sB + (uint32_t)((p * 4 + kt) * 512)));             \
        _Pragma("unroll")                                                         \
        for (int mt = 0; mt < 4; mt++)                                            \
            _Pragma("unroll")                                                     \
            for (int p = 0; p < 2; p++)                                           \
                _Pragma("unroll")                                                 \
                for (int h = 0; h < 2; h++)                                       \
                    mma_fp16(acc[mt][2 * p + h], af[mt], &bfp[p][2 * h]);         \
    }                                                                             \
} while (0)

    LOAD_STAGE(0u, 0);

    float acc[4][4][4];
#pragma unroll
    for (int i = 0; i < 4; i++)
#pragma unroll
        for (int j = 0; j < 4; j++)
#pragma unroll
            for (int q = 0; q < 4; q++) acc[i][j][q] = 0.0f;

    for (int kc = 0; kc < NK; kc += 2) {
        asm volatile("cp.async.wait_group 0;" ::: "memory");
        __syncthreads();
        if (kc + 1 < NK) LOAD_STAGE((uint32_t)S_STAGE, kc + 1);
        COMPUTE(0u);

        asm volatile("cp.async.wait_group 0;" ::: "memory");
        __syncthreads();
        if (kc + 2 < NK) LOAD_STAGE(0u, kc + 2);
        COMPUTE((uint32_t)S_STAGE);
    }
#undef LOAD_STAGE
#undef COMPUTE

    // ---- epilogue (identical mapping to R14; acc[mt][2p+h] == acc[mt][nt]) ----
#pragma unroll
    for (int mt = 0; mt < 4; mt++) {
        if (GELU) {
            uint32_t* C = (uint32_t*)Cv;
            // Two adjacent nt blocks (16 H-cols) form one fp16 A-frag block of H.
#pragma unroll
            for (int j = 0; j < 2; j++) {
                float v[2][4];
#pragma unroll
                for (int h = 0; h < 2; h++) {
                    const int nt = 2 * j + h;
                    const int col0 = wn * 32 + nt * 8 + 2 * tt;
#pragma unroll
                    for (int q = 0; q < 4; q++) {
                        float x = acc[mt][nt][q] + sbias[col0 + (q & 1)];
                        x = 0.5f * x * (1.0f + erff(x * 0.70710678118654752f));
                        v[h][q] = x;
                    }
                }
                uint32_t p0 = pack_h2(v[0][0], v[0][1]);   // row gl,   k 2tt,2tt+1
                uint32_t p1 = pack_h2(v[0][2], v[0][3]);   // row gl+8, k 2tt,2tt+1
                uint32_t p2 = pack_h2(v[1][0], v[1][1]);   // row gl,   k 2tt+8,2tt+9
                uint32_t p3 = pack_h2(v[1][2], v[1][3]);   // row gl+8, k 2tt+8,2tt+9
                const size_t Mtile = (size_t)(row_base >> 4) + wm * 4 + mt;
                const int kb2 = blockIdx.x * 8 + wn * 2 + j;
                uint4* dst = reinterpret_cast<uint4*>(
                    C + (Mtile * (size_t)(N >> 4) + kb2) * 128 + lid * 4);
                *dst = make_uint4(p0, p1, p2, p3);
            }
        } else {
            float* C = (float*)Cv;
#pragma unroll
            for (int nt = 0; nt < 4; nt++) {
                const int col0 = wn * 32 + nt * 8 + 2 * tt;
                float v[4];
#pragma unroll
                for (int q = 0; q < 4; q++)
                    v[q] = acc[mt][nt][q] + sbias[col0 + (q & 1)];
                const int r0 = wm * 64 + mt * 16 + gl;
                long R0 = row_base + r0;
                int c = blockIdx.x * 128 + col0;
                *reinterpret_cast<float2*>(&C[(size_t)R0 * N + c]) = make_float2(v[0], v[1]);
                *reinterpret_cast<float2*>(&C[(size_t)(R0 + 8) * N + c]) = make_float2(v[2], v[3]);
            }
        }
    }
}

// ---------------- launch ----------------
extern "C" void kernel_launch(void* const* d_in, const int* in_sizes, int n_in,
                              void* d_out, int out_size) {
    const float* x  = (const float*)d_in[0];
    const float* w1 = (const float*)d_in[1];
    const float* b1 = (const float*)d_in[2];
    const float* w2 = (const float*)d_in[3];
    const float* b2 = (const float*)d_in[4];
    float* out = (float*)d_out;

    uint32_t *p_xr, *p_w1t, *p_w2t, *p_h;
    cudaGetSymbolAddress((void**)&p_xr,  g_xr);
    cudaGetSymbolAddress((void**)&p_w1t, g_w1t);
    cudaGetSymbolAddress((void**)&p_w2t, g_w2t);
    cudaGetSymbolAddress((void**)&p_h,   g_h);

    cudaFuncSetAttribute(gemm_fp16<true>,  cudaFuncAttributeMaxDynamicSharedMemorySize, DSMEM);
    cudaFuncSetAttribute(gemm_fp16<false>, cudaFuncAttributeMaxDynamicSharedMemorySize, DSMEM);

    // pack x into fp16 A-frag layout (65536 rows, K=1024)
    prep_A<<<dim3(D_MODEL / 128, GROUPS * TOKENS / 16), 256>>>(x, p_xr, D_MODEL);
    // pack w1 [e][1024][4096] (k=d_model, n=d_ff) into fp16 B-pair
    prep_B<<<dim3(D_FF / 256, D_MODEL / 16, NUM_EXPERTS), 256>>>(w1, p_w1t, D_MODEL, D_FF);
    // pack w2 [e][4096][1024] (k=d_ff, n=d_model) into fp16 B-pair
    prep_B<<<dim3(D_MODEL / 256, D_FF / 16, NUM_EXPERTS), 256>>>(w2, p_w2t, D_FF, D_MODEL);

    // GEMM1: per (g,e): [2048 x 1024] @ [1024 x 4096] + b1, gelu -> H (fp16 A-frag)
    gemm_fp16<true><<<dim3(D_FF / 128, CHUNK / 128, GROUPS * NUM_EXPERTS), 256, DSMEM>>>(
        p_xr, p_w1t, b1, p_h, D_MODEL, D_FF);
    // GEMM2: per (g,e): [2048 x 4096] @ [4096 x 1024] + b2 -> out (row-major f32)
    gemm_fp16<false><<<dim3(D_MODEL / 128, CHUNK / 128, GROUPS * NUM_EXPERTS), 256, DSMEM>>>(
        p_h, p_w2t, b2, out, D_FF, D_MODEL);
}

// round 17
// speedup vs baseline: 1.2621x; 1.0326x over previous
#include <cuda_runtime.h>
#include <cuda_fp16.h>
#include <cstdint>
#include <math.h>

#define NUM_EXPERTS 8
#define D_MODEL 1024
#define D_FF 4096
#define GROUPS 4
#define TOKENS 16384
#define CHUNK 2048

// ---------------- scratch (device globals) ----------------
// fp16 fragment-tiled layouts (u32 = half2):
//  A-frag: [mtile(16 rows)][K/16][128 u32]   (16x16 block, lane*4 -> lds.128)
//  B-pair: [ntp(16 cols)][K/16][128 u32]     (two 16x8 frags interleaved, lane*4 -> lds.128)
__device__ uint32_t g_xr [(size_t)(GROUPS * TOKENS / 16) * (D_MODEL / 16) * 128]; // 134 MB
__device__ uint32_t g_w1t[(size_t)(NUM_EXPERTS * D_FF / 16) * (D_MODEL / 16) * 128]; // 67 MB
__device__ uint32_t g_w2t[(size_t)(NUM_EXPERTS * D_MODEL / 16) * (D_FF / 16) * 128]; // 67 MB
__device__ uint32_t g_h  [(size_t)(GROUPS * TOKENS / 16) * (D_FF / 16) * 128];     // 536 MB

// ---------------- helpers ----------------
__device__ __forceinline__ uint32_t smem_u32(const void* p) {
    uint32_t a;
    asm("{ .reg .u64 t; cvta.to.shared.u64 t, %1; cvt.u32.u64 %0, t; }" : "=r"(a) : "l"(p));
    return a;
}

__device__ __forceinline__ uint32_t pack_h2(float lo, float hi) {
    uint32_t u;
    asm("cvt.rn.f16x2.f32 %0, %1, %2;" : "=r"(u) : "f"(hi), "f"(lo));  // d = {hi, lo}
    return u;
}

__device__ __forceinline__ void mma_fp16(float* c, const uint32_t* a, const uint32_t* b) {
    asm volatile(
        "mma.sync.aligned.m16n8k16.row.col.f32.f16.f16.f32 "
        "{%0,%1,%2,%3}, {%4,%5,%6,%7}, {%8,%9}, {%0,%1,%2,%3};"
        : "+f"(c[0]), "+f"(c[1]), "+f"(c[2]), "+f"(c[3])
        : "r"(a[0]), "r"(a[1]), "r"(a[2]), "r"(a[3]), "r"(b[0]), "r"(b[1]));
}

// ---------------- prep kernels (unchanged) ----------------
__global__ void __launch_bounds__(256) prep_A(const float* __restrict__ src,
                                              uint32_t* __restrict__ dst, int K) {
    __shared__ float t[16][132];
    const int mt = blockIdx.y, kb8 = blockIdx.x;
    const int tid = threadIdx.x;
    const int K16 = K >> 4;
#pragma unroll
    for (int i = 0; i < 8; i++) {
        int lin = i * 256 + tid;
        int r = lin >> 7, c = lin & 127;
        t[r][c] = src[(size_t)(mt * 16 + r) * K + kb8 * 128 + c];
    }
    __syncthreads();
#pragma unroll
    for (int i = 0; i < 4; i++) {
        int lin = i * 256 + tid;                 // 1024 u32 outputs
        int kbl = lin >> 7, pos = lin & 127;
        int lane = pos >> 2, reg = pos & 3;
        int gl = lane >> 2, tt = lane & 3;
        int r = gl + (reg & 1) * 8;
        int kl = kbl * 16 + 2 * tt + (reg >> 1) * 8;
        dst[((size_t)mt * K16 + kb8 * 8 + kbl) * 128 + pos] = pack_h2(t[r][kl], t[r][kl + 1]);
    }
}

__global__ void __launch_bounds__(256) prep_B(const float* __restrict__ src,
                                              uint32_t* __restrict__ dst, int K, int N) {
    __shared__ float t[16][260];
    const int kb = blockIdx.y, nb = blockIdx.x, e = blockIdx.z;
    const int tid = threadIdx.x;
    const int K16 = K >> 4;
    const float* sp = src + (size_t)e * K * N;
    uint32_t* dp = dst + (size_t)e * (N >> 4) * K16 * 128;
#pragma unroll
    for (int i = 0; i < 16; i++) {
        int lin = i * 256 + tid;
        int r = lin >> 8, c = lin & 255;
        t[r][c] = sp[(size_t)(kb * 16 + r) * N + nb * 256 + c];
    }
    __syncthreads();
#pragma unroll
    for (int i = 0; i < 8; i++) {
        int lin = i * 256 + tid;                 // 2048 u32 outputs (16 ntp x 128)
        int ntp = lin >> 7, pos = lin & 127;
        int lane = pos >> 2, sub = pos & 3;
        int h = sub >> 1, reg = sub & 1;
        int gl = lane >> 2, tt = lane & 3;
        int n = (2 * ntp + h) * 8 + gl;
        int kl = 2 * tt + reg * 8;
        dp[((size_t)(nb * 16 + ntp) * K16 + kb) * 128 + pos] = pack_h2(t[kl][n], t[kl + 1][n]);
    }
}

// ---------------- GEMM ----------------
// CTA tile 64x128, Kc=64 (4 kt of K=16), 2-stage cp.async, kc unrolled x2, 4 CTAs/SM.
// 4 warps (2M x 2N), warp tile 32x64. Barriers rendezvous only 4 warps; the 4
// co-resident CTAs hit their barriers at independent phases.
static constexpr int S_A_BYTES = 8192;              // 4 mt * 4 kt * 512B
static constexpr int S_B_BYTES = 16384;             // 8 ntp * 4 kt * 512B
static constexpr int S_STAGE   = S_A_BYTES + S_B_BYTES;   // 24576
static constexpr int DSMEM     = 2 * S_STAGE + 512;       // 49664 (x4 CTA = 194KB < 228KB)

template <bool GELU>
__global__ void __launch_bounds__(128, 4)
gemm_fp16(const uint32_t* __restrict__ A, const uint32_t* __restrict__ B,
          const float* __restrict__ bias, void* __restrict__ Cv,
          int K, int N) {
    extern __shared__ char smem[];
    const uint32_t sb = smem_u32(smem);
    const int tid = threadIdx.x;
    const int wid = tid >> 5;
    const int lid = tid & 31;
    const int gl = lid >> 2, tt = lid & 3;
    const int wm = wid & 1;                          // 0/1: M half (32 rows)
    const int wn = wid >> 1;                         // 0/1: N half (64 cols = 4 ntp)

    const int ge = blockIdx.z;
    const int gg = ge >> 3, e = ge & 7;
    const int K16 = K >> 4;
    const long row_base = (long)gg * TOKENS + (long)e * CHUNK + (long)blockIdx.y * 64;
    const uint32_t* Abase = A + (size_t)(row_base >> 4) * K16 * 128;
    const uint32_t* Bbase = B + (size_t)(e * (N >> 4) + blockIdx.x * 8) * K16 * 128;

    // hoisted per-thread copy addressing: 4 groups x 32 lanes
    const int w5 = tid >> 5, cc = tid & 31;
    const size_t tStride = (size_t)K16 * 128;        // u32 per frag-tile row (A and B alike)
    // group handles blk = i*4 + w5; tile = blk>>2, kt = blk&3  (kt == w5&3 fixed per group)
    const uint32_t* pA = Abase + (size_t)(w5 >> 2) * tStride + (w5 & 3) * 128 + cc * 4;
    const uint32_t* pB = Bbase + (size_t)(w5 >> 2) * tStride + (w5 & 3) * 128 + cc * 4;
    const uint32_t aDst = sb + (uint32_t)(w5 * 512 + cc * 16);
    const uint32_t bDst = sb + (uint32_t)(S_A_BYTES + w5 * 512 + cc * 16);

    float* sbias = (float*)(smem + 2 * S_STAGE);
    sbias[tid] = bias[e * N + blockIdx.x * 128 + tid];

    // warp-level lds base offsets (bytes, relative to stage base)
    const uint32_t aw_off = (uint32_t)(wm * 4096 + lid * 16);               // 2 mt x 4 kt x 512
    const uint32_t bw_off = (uint32_t)(S_A_BYTES + wn * 8192 + lid * 16);   // 4 ntp x 4 kt x 512

    const int NK = K >> 6;

#define LOAD_STAGE(ST, KC) do {                                                   \
    const uint32_t _k = (uint32_t)(KC) * 512;                                     \
    _Pragma("unroll")                                                             \
    for (int i = 0; i < 4; i++)                                                   \
        asm volatile("cp.async.cg.shared.global [%0], [%1], 16;"                  \
                     :: "r"(aDst + (ST) + i * 2048),                              \
                        "l"(pA + _k + i * tStride));                              \
    _Pragma("unroll")                                                             \
    for (int i = 0; i < 8; i++)                                                   \
        asm volatile("cp.async.cg.shared.global [%0], [%1], 16;"                  \
                     :: "r"(bDst + (ST) + i * 2048),                              \
                        "l"(pB + _k + i * tStride));                              \
    asm volatile("cp.async.commit_group;" ::: "memory");                          \
} while (0)

#define COMPUTE(ST) do {                                                          \
    const uint32_t sA = sb + (ST) + aw_off;                                       \
    const uint32_t sB = sb + (ST) + bw_off;                                       \
    _Pragma("unroll")                                                             \
    for (int kt = 0; kt < 4; kt++) {                                              \
        uint32_t af[2][4], bfp[4][4];                                             \
        _Pragma("unroll")                                                         \
        for (int mt = 0; mt < 2; mt++)                                            \
            asm volatile("ld.shared.v4.b32 {%0,%1,%2,%3}, [%4];"                  \
                         : "=r"(af[mt][0]), "=r"(af[mt][1]),                      \
                           "=r"(af[mt][2]), "=r"(af[mt][3])                       \
                         : "r"(sA + (uint32_t)((mt * 4 + kt) * 512)));            \
        _Pragma("unroll")                                                         \
        for (int p = 0; p < 4; p++)                                               \
            asm volatile("ld.shared.v4.b32 {%0,%1,%2,%3}, [%4];"                  \
                         : "=r"(bfp[p][0]), "=r"(bfp[p][1]),                      \
                           "=r"(bfp[p][2]), "=r"(bfp[p][3])                       \
                         : "r"(sB + (uint32_t)((p * 4 + kt) * 512)));             \
        _Pragma("unroll")                                                         \
        for (int mt = 0; mt < 2; mt++)                                            \
            _Pragma("unroll")                                                     \
            for (int p = 0; p < 4; p++)                                           \
                _Pragma("unroll")                                                 \
                for (int h = 0; h < 2; h++)                                       \
                    mma_fp16(acc[mt][2 * p + h], af[mt], &bfp[p][2 * h]);         \
    }                                                                             \
} while (0)

    LOAD_STAGE(0u, 0);

    float acc[2][8][4];
#pragma unroll
    for (int i = 0; i < 2; i++)
#pragma unroll
        for (int j = 0; j < 8; j++)
#pragma unroll
            for (int q = 0; q < 4; q++) acc[i][j][q] = 0.0f;

    for (int kc = 0; kc < NK; kc += 2) {
        asm volatile("cp.async.wait_group 0;" ::: "memory");
        __syncthreads();
        if (kc + 1 < NK) LOAD_STAGE((uint32_t)S_STAGE, kc + 1);
        COMPUTE(0u);

        asm volatile("cp.async.wait_group 0;" ::: "memory");
        __syncthreads();
        if (kc + 2 < NK) LOAD_STAGE(0u, kc + 2);
        COMPUTE((uint32_t)S_STAGE);
    }
#undef LOAD_STAGE
#undef COMPUTE

    // ---- epilogue ----
#pragma unroll
    for (int mt = 0; mt < 2; mt++) {
        if (GELU) {
            uint32_t* C = (uint32_t*)Cv;
            // Two adjacent nt blocks (16 H-cols) form one fp16 A-frag block of H.
#pragma unroll
            for (int j = 0; j < 4; j++) {
                float v[2][4];
#pragma unroll
                for (int h = 0; h < 2; h++) {
                    const int nt = 2 * j + h;
                    const int col0 = wn * 64 + nt * 8 + 2 * tt;
#pragma unroll
                    for (int q = 0; q < 4; q++) {
                        float x = acc[mt][nt][q] + sbias[col0 + (q & 1)];
                        x = 0.5f * x * (1.0f + erff(x * 0.70710678118654752f));
                        v[h][q] = x;
                    }
                }
                uint32_t p0 = pack_h2(v[0][0], v[0][1]);   // row gl,   k 2tt,2tt+1
                uint32_t p1 = pack_h2(v[0][2], v[0][3]);   // row gl+8, k 2tt,2tt+1
                uint32_t p2 = pack_h2(v[1][0], v[1][1]);   // row gl,   k 2tt+8,2tt+9
                uint32_t p3 = pack_h2(v[1][2], v[1][3]);   // row gl+8, k 2tt+8,2tt+9
                const size_t Mtile = (size_t)(row_base >> 4) + wm * 2 + mt;
                const int kb2 = blockIdx.x * 8 + wn * 4 + j;
                uint4* dst = reinterpret_cast<uint4*>(
                    C + (Mtile * (size_t)(N >> 4) + kb2) * 128 + lid * 4);
                *dst = make_uint4(p0, p1, p2, p3);
            }
        } else {
            float* C = (float*)Cv;
#pragma unroll
            for (int nt = 0; nt < 8; nt++) {
                const int col0 = wn * 64 + nt * 8 + 2 * tt;
                float v[4];
#pragma unroll
                for (int q = 0; q < 4; q++)
                    v[q] = acc[mt][nt][q] + sbias[col0 + (q & 1)];
                const int r0 = wm * 32 + mt * 16 + gl;
                long R0 = row_base + r0;
                int c = blockIdx.x * 128 + col0;
                *reinterpret_cast<float2*>(&C[(size_t)R0 * N + c]) = make_float2(v[0], v[1]);
                *reinterpret_cast<float2*>(&C[(size_t)(R0 + 8) * N + c]) = make_float2(v[2], v[3]);
            }
        }
    }
}

// ---------------- launch ----------------
extern "C" void kernel_launch(void* const* d_in, const int* in_sizes, int n_in,
                              void* d_out, int out_size) {
    const float* x  = (const float*)d_in[0];
    const float* w1 = (const float*)d_in[1];
    const float* b1 = (const float*)d_in[2];
    const float* w2 = (const float*)d_in[3];
    const float* b2 = (const float*)d_in[4];
    float* out = (float*)d_out;

    uint32_t *p_xr, *p_w1t, *p_w2t, *p_h;
    cudaGetSymbolAddress((void**)&p_xr,  g_xr);
    cudaGetSymbolAddress((void**)&p_w1t, g_w1t);
    cudaGetSymbolAddress((void**)&p_w2t, g_w2t);
    cudaGetSymbolAddress((void**)&p_h,   g_h);

    cudaFuncSetAttribute(gemm_fp16<true>,  cudaFuncAttributeMaxDynamicSharedMemorySize, DSMEM);
    cudaFuncSetAttribute(gemm_fp16<false>, cudaFuncAttributeMaxDynamicSharedMemorySize, DSMEM);

    // pack x into fp16 A-frag layout (65536 rows, K=1024)
    prep_A<<<dim3(D_MODEL / 128, GROUPS * TOKENS / 16), 256>>>(x, p_xr, D_MODEL);
    // pack w1 [e][1024][4096] (k=d_model, n=d_ff) into fp16 B-pair
    prep_B<<<dim3(D_FF / 256, D_MODEL / 16, NUM_EXPERTS), 256>>>(w1, p_w1t, D_MODEL, D_FF);
    // pack w2 [e][4096][1024] (k=d_ff, n=d_model) into fp16 B-pair
    prep_B<<<dim3(D_MODEL / 256, D_FF / 16, NUM_EXPERTS), 256>>>(w2, p_w2t, D_FF, D_MODEL);

    // GEMM1: per (g,e): [2048 x 1024] @ [1024 x 4096] + b1, gelu -> H (fp16 A-frag)
    gemm_fp16<true><<<dim3(D_FF / 128, CHUNK / 64, GROUPS * NUM_EXPERTS), 128, DSMEM>>>(
        p_xr, p_w1t, b1, p_h, D_MODEL, D_FF);
    // GEMM2: per (g,e): [2048 x 4096] @ [4096 x 1024] + b2 -> out (row-major f32)
    gemm_fp16<false><<<dim3(D_MODEL / 128, CHUNK / 64, GROUPS * NUM_EXPERTS), 128, DSMEM>>>(
        p_h, p_w2t, b2, out, D_FF, D_MODEL);
}